// round 11
// baseline (speedup 1.0000x reference)
#include <cuda_runtime.h>

#define F 128
#define NH 4
#define MAX_N 65536
#define MAX_R 512
#define MAX_E 655360

typedef unsigned long long ull;

// ---------------- static scratch (no allocs allowed) ----------------
__device__ float4 d_s4[MAX_N];        // per-node attention scalars, 4 heads
__device__ float4 d_t4[MAX_R];        // per-relation attention scalars, 4 heads
__device__ int    d_deg[MAX_N];       // zero-init at load; k_gather re-zeros for next call
__device__ int    d_off[MAX_N + 1];
__device__ int    d_cursor[MAX_N];
__device__ int    d_bsum[256];        // scan block sums
__device__ int    d_packed[MAX_E];    // src | (rel<<20)
__device__ float4 d_ee[MAX_E];        // edge exp factors, 4 heads

// ---------------- f32x2 packed helpers ----------------
__device__ __forceinline__ ull pk2(float lo, float hi) {
    ull r;
    asm("mov.b64 %0, {%1, %2};" : "=l"(r) : "f"(lo), "f"(hi));
    return r;
}
__device__ __forceinline__ void upk2(float& lo, float& hi, ull v) {
    asm("mov.b64 {%0, %1}, %2;" : "=f"(lo), "=f"(hi) : "l"(v));
}
__device__ __forceinline__ ull f2fma(ull a, ull b, ull c) {
    ull d;
    asm("fma.rn.f32x2 %0, %1, %2, %3;" : "=l"(d) : "l"(a), "l"(b), "l"(c));
    return d;
}

// ---------------- fused front: t-scalars | s-scalars | degree count ----------------
__global__ void __launch_bounds__(128) k_front(const float* __restrict__ h,
                                               const float* __restrict__ inputr,
                                               const float* __restrict__ w,
                                               const float* __restrict__ a,
                                               const int* __restrict__ A,
                                               int N, int R, int E, int TB, int SB) {
    int b = blockIdx.x;
    if (b < TB) {
        int gw   = b * 4 + (threadIdx.x >> 5);
        int lane = threadIdx.x & 31;
        if (gw >= R) return;
        int f0 = lane * 4;
        float4 rv = *(const float4*)(inputr + (size_t)gw * F + f0);
        float p[NH];
#pragma unroll
        for (int i = 0; i < NH; i++) {
            const float* ad = a + (i * 2 + 1) * F + f0;
            p[i] = rv.x * ad[0] + rv.y * ad[1] + rv.z * ad[2] + rv.w * ad[3];
        }
#pragma unroll
        for (int o = 16; o >= 1; o >>= 1)
#pragma unroll
            for (int i = 0; i < NH; i++) p[i] += __shfl_xor_sync(0xffffffffu, p[i], o);
        if (lane == 0) d_t4[gw] = make_float4(p[0], p[1], p[2], p[3]);
    } else if (b < TB + SB) {
        int gw   = (b - TB) * 4 + (threadIdx.x >> 5);
        int lane = threadIdx.x & 31;
        if (gw >= N) return;
        int f0 = lane * 4;
        float4 w0 = *(const float4*)(w + 0 * F + f0);
        float4 w1 = *(const float4*)(w + 1 * F + f0);
        float4 w2 = *(const float4*)(w + 2 * F + f0);
        float W[NH][4];
        W[0][0] = 1.f;            W[0][1] = 1.f;            W[0][2] = 1.f;            W[0][3] = 1.f;
        W[1][0] = w0.x;           W[1][1] = w0.y;           W[1][2] = w0.z;           W[1][3] = w0.w;
        W[2][0] = W[1][0] * w1.x; W[2][1] = W[1][1] * w1.y; W[2][2] = W[1][2] * w1.z; W[2][3] = W[1][3] * w1.w;
        W[3][0] = W[2][0] * w2.x; W[3][1] = W[2][1] * w2.y; W[3][2] = W[2][2] * w2.z; W[3][3] = W[2][3] * w2.w;
        float4 hv = *(const float4*)(h + (size_t)gw * F + f0);
        float hvv[4] = {hv.x, hv.y, hv.z, hv.w};
        float p[NH];
#pragma unroll
        for (int i = 0; i < NH; i++) {
            const float* as = a + (i * 2 + 0) * F + f0;
            float acc = 0.f;
#pragma unroll
            for (int j = 0; j < 4; j++) acc = fmaf(hvv[j] * W[i][j], as[j], acc);
            p[i] = acc;
        }
#pragma unroll
        for (int o = 16; o >= 1; o >>= 1)
#pragma unroll
            for (int i = 0; i < NH; i++) p[i] += __shfl_xor_sync(0xffffffffu, p[i], o);
        if (lane == 0) d_s4[gw] = make_float4(p[0], p[1], p[2], p[3]);
    } else {
        int e = (b - TB - SB) * 128 + threadIdx.x;
        if (e < E) atomicAdd(&d_deg[A[e]], 1);
    }
}

// ---------------- multi-block scan, phase 1: per-block sums ----------------
__global__ void __launch_bounds__(256) k_scan1(int N) {
    int i = blockIdx.x * 256 + threadIdx.x;
    int v = (i < N) ? d_deg[i] : 0;
    __shared__ int sw[8];
    int lane = threadIdx.x & 31, wid = threadIdx.x >> 5;
#pragma unroll
    for (int o = 16; o >= 1; o >>= 1) v += __shfl_xor_sync(0xffffffffu, v, o);
    if (lane == 0) sw[wid] = v;
    __syncthreads();
    if (wid == 0) {
        int s = (lane < 8) ? sw[lane] : 0;
#pragma unroll
        for (int o = 4; o >= 1; o >>= 1) s += __shfl_xor_sync(0xffffffffu, s, o);
        if (lane == 0) d_bsum[blockIdx.x] = s;
    }
}

// ---------------- phase 2: exclusive scan of block sums (NB <= 256) ----------------
__global__ void __launch_bounds__(256) k_scan2(int NB, int N) {
    __shared__ int sh[256];
    int t = threadIdx.x;
    int v = (t < NB) ? d_bsum[t] : 0;
    sh[t] = v;
    __syncthreads();
#pragma unroll
    for (int d = 1; d < 256; d <<= 1) {
        int u = (t >= d) ? sh[t - d] : 0;
        __syncthreads();
        sh[t] += u;
        __syncthreads();
    }
    if (t < NB) d_bsum[t] = sh[t] - v;   // exclusive base per block
    if (t == 255) d_off[N] = sh[255];    // grand total
}

// ---------------- phase 3: block-local scan + write off/cursor ----------------
__global__ void __launch_bounds__(256) k_scan3(int N) {
    __shared__ int sh[256];
    int t = threadIdx.x;
    int i = blockIdx.x * 256 + t;
    int v = (i < N) ? d_deg[i] : 0;
    sh[t] = v;
    __syncthreads();
#pragma unroll
    for (int d = 1; d < 256; d <<= 1) {
        int u = (t >= d) ? sh[t - d] : 0;
        __syncthreads();
        sh[t] += u;
        __syncthreads();
    }
    if (i < N) {
        int e = sh[t] - v + d_bsum[blockIdx.x];
        d_off[i]    = e;
        d_cursor[i] = e;
    }
}

// ---------------- scatter edges into CSR + compute per-edge exp factors ----------------
__global__ void __launch_bounds__(256) k_scatter(const int* __restrict__ A, int E) {
    int e = blockIdx.x * blockDim.x + threadIdx.x;
    if (e >= E) return;
    int dst = A[e];
    int rel = A[(size_t)E + e];
    int src = A[2 * (size_t)E + e];
    float4 s4 = d_s4[src];
    float4 t4 = d_t4[rel];
    float sv[4] = {s4.x, s4.y, s4.z, s4.w};
    float tv[4] = {t4.x, t4.y, t4.z, t4.w};
    float ev[4];
#pragma unroll
    for (int i = 0; i < 4; i++) {
        float x = sv[i] + tv[i];
        float l = x > 0.f ? x : 0.2f * x;   // leaky_relu
        ev[i]   = __expf(-l);
    }
    int pos = atomicAdd(&d_cursor[dst], 1);
    d_packed[pos] = src | (rel << 20);
    d_ee[pos]     = make_float4(ev[0], ev[1], ev[2], ev[3]);
}

// ---------------- gather: persistent blocks, r-half staged in SMEM ----------------
// grid = 2*148 blocks, 512 threads. blockIdx&1 = feature half; blocks stride nodes.
__global__ void __launch_bounds__(512, 1) k_gather(const float* __restrict__ h,
                                                   const float* __restrict__ r,
                                                   const float* __restrict__ w,
                                                   float* __restrict__ out,
                                                   int N, int R, int NBP) {
    extern __shared__ float sr[];   // [R][64] this half's relation features
    int half  = blockIdx.x & 1;
    int bpair = blockIdx.x >> 1;    // 0..NBP-1
    int tid   = threadIdx.x;
    int wid   = tid >> 5;           // 0..15
    int lane  = tid & 31;
    int f0    = half * 64 + lane * 2;

    // stage this feature-half of the relation table into smem (coalesced)
    for (int i = tid; i < R * 64; i += 512) {
        int row = i >> 6, col = i & 63;
        sr[i] = r[(size_t)row * F + half * 64 + col];
    }
    __syncthreads();

    // diag cumulative products: depend only on f0 -> hoist out of node loop
    float2 w0 = *(const float2*)(w + 0 * F + f0);
    float2 w1 = *(const float2*)(w + 1 * F + f0);
    float2 w2 = *(const float2*)(w + 2 * F + f0);
    float W[4][2];
    W[0][0] = 1.f;            W[0][1] = 1.f;
    W[1][0] = w0.x;           W[1][1] = w0.y;
    W[2][0] = W[1][0] * w1.x; W[2][1] = W[1][1] * w1.y;
    W[3][0] = W[2][0] * w2.x; W[3][1] = W[2][1] * w2.y;

    int stride = NBP * 16;
    for (int n = bpair * 16 + wid; n < N; n += stride) {
        if (half == 0 && lane == 0) d_deg[n] = 0;  // reset for next replay

        ull aH[4] = {0ull, 0ull, 0ull, 0ull};
        ull aR[4] = {0ull, 0ull, 0ull, 0ull};
        float rs[4] = {0.f, 0.f, 0.f, 0.f};

        int kb = d_off[n], ke = d_off[n + 1];
        int k = kb;

        // depth-4: 4 meta loads -> 4 h loads (L2) + 4 r loads (smem) -> FMAs
        for (; k + 3 < ke; k += 4) {
            int    p0 = d_packed[k];
            int    p1 = d_packed[k + 1];
            int    p2 = d_packed[k + 2];
            int    p3 = d_packed[k + 3];
            float4 e0 = d_ee[k];
            float4 e1 = d_ee[k + 1];
            float4 e2 = d_ee[k + 2];
            float4 e3 = d_ee[k + 3];
            ull h0 = *(const ull*)(h + (size_t)(p0 & 0xFFFFF) * F + f0);
            ull h1 = *(const ull*)(h + (size_t)(p1 & 0xFFFFF) * F + f0);
            ull h2 = *(const ull*)(h + (size_t)(p2 & 0xFFFFF) * F + f0);
            ull h3 = *(const ull*)(h + (size_t)(p3 & 0xFFFFF) * F + f0);
            ull r0 = *(const ull*)(sr + (p0 >> 20) * 64 + lane * 2);
            ull r1 = *(const ull*)(sr + (p1 >> 20) * 64 + lane * 2);
            ull r2 = *(const ull*)(sr + (p2 >> 20) * 64 + lane * 2);
            ull r3 = *(const ull*)(sr + (p3 >> 20) * 64 + lane * 2);
            float ev0[4] = {e0.x, e0.y, e0.z, e0.w};
            float ev1[4] = {e1.x, e1.y, e1.z, e1.w};
            float ev2[4] = {e2.x, e2.y, e2.z, e2.w};
            float ev3[4] = {e3.x, e3.y, e3.z, e3.w};
#pragma unroll
            for (int i = 0; i < 4; i++) {
                ull eb0 = pk2(ev0[i], ev0[i]);
                ull eb1 = pk2(ev1[i], ev1[i]);
                ull eb2 = pk2(ev2[i], ev2[i]);
                ull eb3 = pk2(ev3[i], ev3[i]);
                aH[i] = f2fma(h0, eb0, aH[i]);
                aR[i] = f2fma(r0, eb0, aR[i]);
                aH[i] = f2fma(h1, eb1, aH[i]);
                aR[i] = f2fma(r1, eb1, aR[i]);
                aH[i] = f2fma(h2, eb2, aH[i]);
                aR[i] = f2fma(r2, eb2, aR[i]);
                aH[i] = f2fma(h3, eb3, aH[i]);
                aR[i] = f2fma(r3, eb3, aR[i]);
                rs[i] += (ev0[i] + ev1[i]) + (ev2[i] + ev3[i]);
            }
        }
        for (; k < ke; k++) {
            int    p0 = d_packed[k];
            float4 e0 = d_ee[k];
            ull h0 = *(const ull*)(h + (size_t)(p0 & 0xFFFFF) * F + f0);
            ull r0 = *(const ull*)(sr + (p0 >> 20) * 64 + lane * 2);
            float ev0[4] = {e0.x, e0.y, e0.z, e0.w};
#pragma unroll
            for (int i = 0; i < 4; i++) {
                ull eb = pk2(ev0[i], ev0[i]);
                aH[i] = f2fma(h0, eb, aH[i]);
                aR[i] = f2fma(r0, eb, aR[i]);
                rs[i] += ev0[i];
            }
        }

#pragma unroll
        for (int i = 0; i < 4; i++) {
            float inv = 1.f / rs[i];  // every node has >=1 in-edge by construction
            float a0, a1, b0, b1;
            upk2(a0, a1, aH[i]);
            upk2(b0, b1, aR[i]);
            float2 o = make_float2((W[i][0] * a0 - b0) * inv,
                                   (W[i][1] * a1 - b1) * inv);
            *(float2*)(out + ((size_t)i * N + n) * F + f0) = o;
        }
    }
}

extern "C" void kernel_launch(void* const* d_in, const int* in_sizes, int n_in,
                              void* d_out, int out_size) {
    const float* h      = (const float*)d_in[0];
    const float* inputr = (const float*)d_in[1];
    const float* w      = (const float*)d_in[2];
    const float* a      = (const float*)d_in[3];
    const int*   A      = (const int*)d_in[4];
    int N = in_sizes[0] / F;
    int R = in_sizes[1] / F;
    int E = in_sizes[4] / 3;
    float* out = (float*)d_out;

    int TB = (R + 3) / 4;            // t blocks (4 warps each)
    int SB = (N + 3) / 4;            // s blocks (4 warps each)
    int CB = (E + 127) / 128;        // count blocks
    int NB = (N + 255) / 256;        // scan blocks (<= 256)

    int smem = R * 64 * (int)sizeof(float);   // 128 KB for R=500
    static int smem_set = 0;
    if (!smem_set) {
        cudaFuncSetAttribute(k_gather, cudaFuncAttributeMaxDynamicSharedMemorySize,
                             MAX_R * 64 * (int)sizeof(float));
        smem_set = 1;
    }

    k_front<<<TB + SB + CB, 128>>>(h, inputr, w, a, A, N, R, E, TB, SB);
    k_scan1<<<NB, 256>>>(N);
    k_scan2<<<1, 256>>>(NB, N);
    k_scan3<<<NB, 256>>>(N);
    k_scatter<<<(E + 255) / 256, 256>>>(A, E);
    int NBP = 148;                   // block pairs; grid = 2*NBP
    k_gather<<<2 * NBP, 512, smem>>>(h, inputr, w, out, N, R, NBP);
}

// round 12
// speedup vs baseline: 1.1080x; 1.1080x over previous
#include <cuda_runtime.h>

#define F 128
#define NH 4
#define MAX_N 65536
#define MAX_R 512
#define MAX_E 655360

typedef unsigned long long ull;

// ---------------- static scratch (no allocs allowed) ----------------
__device__ float4 d_s4[MAX_N];        // per-node attention scalars, 4 heads
__device__ float4 d_t4[MAX_R];        // per-relation attention scalars, 4 heads
__device__ int    d_deg[MAX_N];       // zero-init at load; k_gather re-zeros for next call
__device__ int    d_off[MAX_N + 1];
__device__ int    d_cursor[MAX_N];
__device__ int    d_bsum[256];        // scan block sums
__device__ float  d_rowsum[MAX_N * 4];// per-node, per-head softmax denominators
__device__ int    d_packed[MAX_E];    // src | (rel<<20)
__device__ float4 d_ee[MAX_E];        // edge exp factors, 4 heads

// ---------------- f32x2 packed helpers ----------------
__device__ __forceinline__ ull pk2(float lo, float hi) {
    ull r;
    asm("mov.b64 %0, {%1, %2};" : "=l"(r) : "f"(lo), "f"(hi));
    return r;
}
__device__ __forceinline__ void upk2(float& lo, float& hi, ull v) {
    asm("mov.b64 {%0, %1}, %2;" : "=f"(lo), "=f"(hi) : "l"(v));
}
__device__ __forceinline__ ull f2fma(ull a, ull b, ull c) {
    ull d;
    asm("fma.rn.f32x2 %0, %1, %2, %3;" : "=l"(d) : "l"(a), "l"(b), "l"(c));
    return d;
}

// ---------------- fused front: t-scalars | s-scalars | degree count ----------------
__global__ void __launch_bounds__(128) k_front(const float* __restrict__ h,
                                               const float* __restrict__ inputr,
                                               const float* __restrict__ w,
                                               const float* __restrict__ a,
                                               const int* __restrict__ A,
                                               int N, int R, int E, int TB, int SB) {
    int b = blockIdx.x;
    if (b == 0 && threadIdx.x == 0) d_off[N] = E;   // grand total is known
    if (b < TB) {
        int gw   = b * 4 + (threadIdx.x >> 5);
        int lane = threadIdx.x & 31;
        if (gw >= R) return;
        int f0 = lane * 4;
        float4 rv = *(const float4*)(inputr + (size_t)gw * F + f0);
        float p[NH];
#pragma unroll
        for (int i = 0; i < NH; i++) {
            const float* ad = a + (i * 2 + 1) * F + f0;
            p[i] = rv.x * ad[0] + rv.y * ad[1] + rv.z * ad[2] + rv.w * ad[3];
        }
#pragma unroll
        for (int o = 16; o >= 1; o >>= 1)
#pragma unroll
            for (int i = 0; i < NH; i++) p[i] += __shfl_xor_sync(0xffffffffu, p[i], o);
        if (lane == 0) d_t4[gw] = make_float4(p[0], p[1], p[2], p[3]);
    } else if (b < TB + SB) {
        int gw   = (b - TB) * 4 + (threadIdx.x >> 5);
        int lane = threadIdx.x & 31;
        if (gw >= N) return;
        int f0 = lane * 4;
        float4 w0 = *(const float4*)(w + 0 * F + f0);
        float4 w1 = *(const float4*)(w + 1 * F + f0);
        float4 w2 = *(const float4*)(w + 2 * F + f0);
        float W[NH][4];
        W[0][0] = 1.f;            W[0][1] = 1.f;            W[0][2] = 1.f;            W[0][3] = 1.f;
        W[1][0] = w0.x;           W[1][1] = w0.y;           W[1][2] = w0.z;           W[1][3] = w0.w;
        W[2][0] = W[1][0] * w1.x; W[2][1] = W[1][1] * w1.y; W[2][2] = W[1][2] * w1.z; W[2][3] = W[1][3] * w1.w;
        W[3][0] = W[2][0] * w2.x; W[3][1] = W[2][1] * w2.y; W[3][2] = W[2][2] * w2.z; W[3][3] = W[2][3] * w2.w;
        float4 hv = *(const float4*)(h + (size_t)gw * F + f0);
        float hvv[4] = {hv.x, hv.y, hv.z, hv.w};
        float p[NH];
#pragma unroll
        for (int i = 0; i < NH; i++) {
            const float* as = a + (i * 2 + 0) * F + f0;
            float acc = 0.f;
#pragma unroll
            for (int j = 0; j < 4; j++) acc = fmaf(hvv[j] * W[i][j], as[j], acc);
            p[i] = acc;
        }
#pragma unroll
        for (int o = 16; o >= 1; o >>= 1)
#pragma unroll
            for (int i = 0; i < NH; i++) p[i] += __shfl_xor_sync(0xffffffffu, p[i], o);
        if (lane == 0) d_s4[gw] = make_float4(p[0], p[1], p[2], p[3]);
    } else {
        int e = (b - TB - SB) * 128 + threadIdx.x;
        if (e < E) atomicAdd(&d_deg[A[e]], 1);
    }
}

// ---------------- scan phase 1: per-block sums + zero rowsum ----------------
__global__ void __launch_bounds__(256) k_scan1(int N) {
    int i = blockIdx.x * 256 + threadIdx.x;
    int v = 0;
    if (i < N) {
        v = d_deg[i];
        *(float4*)(d_rowsum + 4 * i) = make_float4(0.f, 0.f, 0.f, 0.f);
    }
    __shared__ int sw[8];
    int lane = threadIdx.x & 31, wid = threadIdx.x >> 5;
    int s = v;
#pragma unroll
    for (int o = 16; o >= 1; o >>= 1) s += __shfl_xor_sync(0xffffffffu, s, o);
    if (lane == 0) sw[wid] = s;
    __syncthreads();
    if (wid == 0) {
        int t = (lane < 8) ? sw[lane] : 0;
#pragma unroll
        for (int o = 4; o >= 1; o >>= 1) t += __shfl_xor_sync(0xffffffffu, t, o);
        if (lane == 0) d_bsum[blockIdx.x] = t;
    }
}

// ---------------- scan phase 2: self-computed base + local scan ----------------
__global__ void __launch_bounds__(256) k_scan3(int N) {
    __shared__ int sh[256];
    __shared__ int sbase;
    int t = threadIdx.x;

    // base = sum of predecessor block sums (NB <= 256, so one per thread)
    int bp = (t < (int)blockIdx.x) ? d_bsum[t] : 0;
    {
        int lane = t & 31, wid = t >> 5;
        __shared__ int sw[8];
#pragma unroll
        for (int o = 16; o >= 1; o >>= 1) bp += __shfl_xor_sync(0xffffffffu, bp, o);
        if (lane == 0) sw[wid] = bp;
        __syncthreads();
        if (wid == 0) {
            int s = (lane < 8) ? sw[lane] : 0;
#pragma unroll
            for (int o = 4; o >= 1; o >>= 1) s += __shfl_xor_sync(0xffffffffu, s, o);
            if (lane == 0) sbase = s;
        }
    }

    int i = blockIdx.x * 256 + t;
    int v = (i < N) ? d_deg[i] : 0;
    sh[t] = v;
    __syncthreads();
#pragma unroll
    for (int d = 1; d < 256; d <<= 1) {
        int u = (t >= d) ? sh[t - d] : 0;
        __syncthreads();
        sh[t] += u;
        __syncthreads();
    }
    if (i < N) {
        int e = sh[t] - v + sbase;
        d_off[i]    = e;
        d_cursor[i] = e;
    }
}

// ---------------- scatter: CSR fill + exp factors + rowsum atomics ----------------
__global__ void __launch_bounds__(256) k_scatter(const int* __restrict__ A, int E) {
    int e = blockIdx.x * blockDim.x + threadIdx.x;
    if (e >= E) return;
    int dst = A[e];
    int rel = A[(size_t)E + e];
    int src = A[2 * (size_t)E + e];
    float4 s4 = d_s4[src];
    float4 t4 = d_t4[rel];
    float sv[4] = {s4.x, s4.y, s4.z, s4.w};
    float tv[4] = {t4.x, t4.y, t4.z, t4.w};
    float ev[4];
#pragma unroll
    for (int i = 0; i < 4; i++) {
        float x = sv[i] + tv[i];
        float l = x > 0.f ? x : 0.2f * x;   // leaky_relu
        ev[i]   = __expf(-l);
    }
    int pos = atomicAdd(&d_cursor[dst], 1);
    d_packed[pos] = src | (rel << 20);
    d_ee[pos]     = make_float4(ev[0], ev[1], ev[2], ev[3]);
#pragma unroll
    for (int i = 0; i < 4; i++) atomicAdd(&d_rowsum[dst * 4 + i], ev[i]);
}

// ---------------- gather: 2 warps/dst feature-split, depth-4, no rowsum work ----------------
__global__ void __launch_bounds__(256, 4) k_gather(const float* __restrict__ h,
                                                   const float* __restrict__ r,
                                                   const float* __restrict__ w,
                                                   float* __restrict__ out, int N) {
    int gw   = (blockIdx.x * blockDim.x + threadIdx.x) >> 5;
    int lane = threadIdx.x & 31;
    int n    = gw >> 1;
    int half = gw & 1;                 // feature half: 0 -> [0,64), 1 -> [64,128)
    if (n >= N) return;
    int f0 = half * 64 + lane * 2;

    if (half == 0 && lane == 0) d_deg[n] = 0;  // reset for next replay

    // cumulative diag products, 2 features per lane, all 4 heads
    float2 w0 = *(const float2*)(w + 0 * F + f0);
    float2 w1 = *(const float2*)(w + 1 * F + f0);
    float2 w2 = *(const float2*)(w + 2 * F + f0);
    float W[4][2];
    W[0][0] = 1.f;            W[0][1] = 1.f;
    W[1][0] = w0.x;           W[1][1] = w0.y;
    W[2][0] = W[1][0] * w1.x; W[2][1] = W[1][1] * w1.y;
    W[3][0] = W[2][0] * w2.x; W[3][1] = W[2][1] * w2.y;

    float4 rsv = *(const float4*)(d_rowsum + 4 * n);   // softmax denominators

    ull aH[4] = {0ull, 0ull, 0ull, 0ull};
    ull aR[4] = {0ull, 0ull, 0ull, 0ull};

    int kb = d_off[n], ke = d_off[n + 1];
    int k = kb;

    // depth-4: 4 meta loads -> 8 gather loads -> FMAs. Two waits per 4 edges.
    for (; k + 3 < ke; k += 4) {
        int    p0 = d_packed[k];
        int    p1 = d_packed[k + 1];
        int    p2 = d_packed[k + 2];
        int    p3 = d_packed[k + 3];
        float4 e0 = d_ee[k];
        float4 e1 = d_ee[k + 1];
        float4 e2 = d_ee[k + 2];
        float4 e3 = d_ee[k + 3];
        ull h0 = *(const ull*)(h + (size_t)(p0 & 0xFFFFF) * F + f0);
        ull r0 = *(const ull*)(r + (size_t)(p0 >> 20) * F + f0);
        ull h1 = *(const ull*)(h + (size_t)(p1 & 0xFFFFF) * F + f0);
        ull r1 = *(const ull*)(r + (size_t)(p1 >> 20) * F + f0);
        ull h2 = *(const ull*)(h + (size_t)(p2 & 0xFFFFF) * F + f0);
        ull r2 = *(const ull*)(r + (size_t)(p2 >> 20) * F + f0);
        ull h3 = *(const ull*)(h + (size_t)(p3 & 0xFFFFF) * F + f0);
        ull r3 = *(const ull*)(r + (size_t)(p3 >> 20) * F + f0);
        float ev0[4] = {e0.x, e0.y, e0.z, e0.w};
        float ev1[4] = {e1.x, e1.y, e1.z, e1.w};
        float ev2[4] = {e2.x, e2.y, e2.z, e2.w};
        float ev3[4] = {e3.x, e3.y, e3.z, e3.w};
#pragma unroll
        for (int i = 0; i < 4; i++) {
            ull eb0 = pk2(ev0[i], ev0[i]);
            ull eb1 = pk2(ev1[i], ev1[i]);
            ull eb2 = pk2(ev2[i], ev2[i]);
            ull eb3 = pk2(ev3[i], ev3[i]);
            aH[i] = f2fma(h0, eb0, aH[i]);
            aR[i] = f2fma(r0, eb0, aR[i]);
            aH[i] = f2fma(h1, eb1, aH[i]);
            aR[i] = f2fma(r1, eb1, aR[i]);
            aH[i] = f2fma(h2, eb2, aH[i]);
            aR[i] = f2fma(r2, eb2, aR[i]);
            aH[i] = f2fma(h3, eb3, aH[i]);
            aR[i] = f2fma(r3, eb3, aR[i]);
        }
    }
    // remainder (<= 3 edges)
    for (; k < ke; k++) {
        int    p0 = d_packed[k];
        float4 e0 = d_ee[k];
        ull h0 = *(const ull*)(h + (size_t)(p0 & 0xFFFFF) * F + f0);
        ull r0 = *(const ull*)(r + (size_t)(p0 >> 20) * F + f0);
        float ev0[4] = {e0.x, e0.y, e0.z, e0.w};
#pragma unroll
        for (int i = 0; i < 4; i++) {
            ull eb = pk2(ev0[i], ev0[i]);
            aH[i] = f2fma(h0, eb, aH[i]);
            aR[i] = f2fma(r0, eb, aR[i]);
        }
    }

    float rsarr[4] = {rsv.x, rsv.y, rsv.z, rsv.w};
#pragma unroll
    for (int i = 0; i < 4; i++) {
        float inv = 1.f / rsarr[i];  // every node has >=1 in-edge by construction
        float a0, a1, b0, b1;
        upk2(a0, a1, aH[i]);
        upk2(b0, b1, aR[i]);
        float2 o = make_float2((W[i][0] * a0 - b0) * inv,
                               (W[i][1] * a1 - b1) * inv);
        *(float2*)(out + ((size_t)i * N + n) * F + f0) = o;
    }
}

extern "C" void kernel_launch(void* const* d_in, const int* in_sizes, int n_in,
                              void* d_out, int out_size) {
    const float* h      = (const float*)d_in[0];
    const float* inputr = (const float*)d_in[1];
    const float* w      = (const float*)d_in[2];
    const float* a      = (const float*)d_in[3];
    const int*   A      = (const int*)d_in[4];
    int N = in_sizes[0] / F;
    int R = in_sizes[1] / F;
    int E = in_sizes[4] / 3;
    float* out = (float*)d_out;

    int TB = (R + 3) / 4;            // t blocks (4 warps each)
    int SB = (N + 3) / 4;            // s blocks (4 warps each)
    int CB = (E + 127) / 128;        // count blocks
    int NB = (N + 255) / 256;        // scan blocks (<= 256)
    k_front<<<TB + SB + CB, 128>>>(h, inputr, w, a, A, N, R, E, TB, SB);
    k_scan1<<<NB, 256>>>(N);
    k_scan3<<<NB, 256>>>(N);
    k_scatter<<<(E + 255) / 256, 256>>>(A, E);
    k_gather<<<(2 * N + 7) / 8, 256>>>(h, inputr, w, out, N);
}

// round 13
// speedup vs baseline: 1.1915x; 1.0753x over previous
#include <cuda_runtime.h>

#define F 128
#define NH 4
#define MAX_N 65536
#define MAX_R 512
#define MAX_E 655360

typedef unsigned long long ull;

// ---------------- static scratch (no allocs allowed) ----------------
__device__ float4 d_s4[MAX_N];        // per-node attention scalars, 4 heads
__device__ float4 d_t4[MAX_R];        // per-relation attention scalars, 4 heads
__device__ int    d_deg[MAX_N];       // zero-init at load; k_gather re-zeros for next call
__device__ int    d_off[MAX_N + 1];
__device__ int    d_cursor[MAX_N];
__device__ int    d_bsum[256];        // scan block sums
__device__ int    d_packed[MAX_E];    // src | (rel<<20)
__device__ float4 d_ee[MAX_E];        // edge exp factors, 4 heads

// ---------------- f32x2 packed helpers ----------------
__device__ __forceinline__ ull pk2(float lo, float hi) {
    ull r;
    asm("mov.b64 %0, {%1, %2};" : "=l"(r) : "f"(lo), "f"(hi));
    return r;
}
__device__ __forceinline__ void upk2(float& lo, float& hi, ull v) {
    asm("mov.b64 {%0, %1}, %2;" : "=f"(lo), "=f"(hi) : "l"(v));
}
__device__ __forceinline__ ull f2fma(ull a, ull b, ull c) {
    ull d;
    asm("fma.rn.f32x2 %0, %1, %2, %3;" : "=l"(d) : "l"(a), "l"(b), "l"(c));
    return d;
}

// ---------------- fused front: t-scalars | s-scalars | degree count ----------------
__global__ void __launch_bounds__(128) k_front(const float* __restrict__ h,
                                               const float* __restrict__ inputr,
                                               const float* __restrict__ w,
                                               const float* __restrict__ a,
                                               const int* __restrict__ A,
                                               int N, int R, int E, int TB, int SB) {
    int b = blockIdx.x;
    if (b == 0 && threadIdx.x == 0) d_off[N] = E;   // grand total is known
    if (b < TB) {
        int gw   = b * 4 + (threadIdx.x >> 5);
        int lane = threadIdx.x & 31;
        if (gw >= R) return;
        int f0 = lane * 4;
        float4 rv = *(const float4*)(inputr + (size_t)gw * F + f0);
        float p[NH];
#pragma unroll
        for (int i = 0; i < NH; i++) {
            const float* ad = a + (i * 2 + 1) * F + f0;
            p[i] = rv.x * ad[0] + rv.y * ad[1] + rv.z * ad[2] + rv.w * ad[3];
        }
#pragma unroll
        for (int o = 16; o >= 1; o >>= 1)
#pragma unroll
            for (int i = 0; i < NH; i++) p[i] += __shfl_xor_sync(0xffffffffu, p[i], o);
        if (lane == 0) d_t4[gw] = make_float4(p[0], p[1], p[2], p[3]);
    } else if (b < TB + SB) {
        int gw   = (b - TB) * 4 + (threadIdx.x >> 5);
        int lane = threadIdx.x & 31;
        if (gw >= N) return;
        int f0 = lane * 4;
        float4 w0 = *(const float4*)(w + 0 * F + f0);
        float4 w1 = *(const float4*)(w + 1 * F + f0);
        float4 w2 = *(const float4*)(w + 2 * F + f0);
        float W[NH][4];
        W[0][0] = 1.f;            W[0][1] = 1.f;            W[0][2] = 1.f;            W[0][3] = 1.f;
        W[1][0] = w0.x;           W[1][1] = w0.y;           W[1][2] = w0.z;           W[1][3] = w0.w;
        W[2][0] = W[1][0] * w1.x; W[2][1] = W[1][1] * w1.y; W[2][2] = W[1][2] * w1.z; W[2][3] = W[1][3] * w1.w;
        W[3][0] = W[2][0] * w2.x; W[3][1] = W[2][1] * w2.y; W[3][2] = W[2][2] * w2.z; W[3][3] = W[2][3] * w2.w;
        float4 hv = *(const float4*)(h + (size_t)gw * F + f0);
        float hvv[4] = {hv.x, hv.y, hv.z, hv.w};
        float p[NH];
#pragma unroll
        for (int i = 0; i < NH; i++) {
            const float* as = a + (i * 2 + 0) * F + f0;
            float acc = 0.f;
#pragma unroll
            for (int j = 0; j < 4; j++) acc = fmaf(hvv[j] * W[i][j], as[j], acc);
            p[i] = acc;
        }
#pragma unroll
        for (int o = 16; o >= 1; o >>= 1)
#pragma unroll
            for (int i = 0; i < NH; i++) p[i] += __shfl_xor_sync(0xffffffffu, p[i], o);
        if (lane == 0) d_s4[gw] = make_float4(p[0], p[1], p[2], p[3]);
    } else {
        int e = (b - TB - SB) * 128 + threadIdx.x;
        if (e < E) atomicAdd(&d_deg[A[e]], 1);
    }
}

// ---------------- scan phase 1: per-block sums ----------------
__global__ void __launch_bounds__(256) k_scan1(int N) {
    int i = blockIdx.x * 256 + threadIdx.x;
    int v = (i < N) ? d_deg[i] : 0;
    __shared__ int sw[8];
    int lane = threadIdx.x & 31, wid = threadIdx.x >> 5;
    int s = v;
#pragma unroll
    for (int o = 16; o >= 1; o >>= 1) s += __shfl_xor_sync(0xffffffffu, s, o);
    if (lane == 0) sw[wid] = s;
    __syncthreads();
    if (wid == 0) {
        int t = (lane < 8) ? sw[lane] : 0;
#pragma unroll
        for (int o = 4; o >= 1; o >>= 1) t += __shfl_xor_sync(0xffffffffu, t, o);
        if (lane == 0) d_bsum[blockIdx.x] = t;
    }
}

// ---------------- scan phase 2: self-computed base + local scan ----------------
__global__ void __launch_bounds__(256) k_scan3(int N) {
    __shared__ int sh[256];
    __shared__ int sbase;
    int t = threadIdx.x;

    // base = sum of predecessor block sums (NB <= 256, so one per thread)
    int bp = (t < (int)blockIdx.x) ? d_bsum[t] : 0;
    {
        int lane = t & 31, wid = t >> 5;
        __shared__ int sw[8];
#pragma unroll
        for (int o = 16; o >= 1; o >>= 1) bp += __shfl_xor_sync(0xffffffffu, bp, o);
        if (lane == 0) sw[wid] = bp;
        __syncthreads();
        if (wid == 0) {
            int s = (lane < 8) ? sw[lane] : 0;
#pragma unroll
            for (int o = 4; o >= 1; o >>= 1) s += __shfl_xor_sync(0xffffffffu, s, o);
            if (lane == 0) sbase = s;
        }
    }

    int i = blockIdx.x * 256 + t;
    int v = (i < N) ? d_deg[i] : 0;
    sh[t] = v;
    __syncthreads();
#pragma unroll
    for (int d = 1; d < 256; d <<= 1) {
        int u = (t >= d) ? sh[t - d] : 0;
        __syncthreads();
        sh[t] += u;
        __syncthreads();
    }
    if (i < N) {
        int e = sh[t] - v + sbase;
        d_off[i]    = e;
        d_cursor[i] = e;
    }
}

// ---------------- scatter edges into CSR + compute per-edge exp factors ----------------
__global__ void __launch_bounds__(256) k_scatter(const int* __restrict__ A, int E) {
    int e = blockIdx.x * blockDim.x + threadIdx.x;
    if (e >= E) return;
    int dst = A[e];
    int rel = A[(size_t)E + e];
    int src = A[2 * (size_t)E + e];
    float4 s4 = d_s4[src];
    float4 t4 = d_t4[rel];
    float sv[4] = {s4.x, s4.y, s4.z, s4.w};
    float tv[4] = {t4.x, t4.y, t4.z, t4.w};
    float ev[4];
#pragma unroll
    for (int i = 0; i < 4; i++) {
        float x = sv[i] + tv[i];
        float l = x > 0.f ? x : 0.2f * x;   // leaky_relu
        ev[i]   = __expf(-l);
    }
    int pos = atomicAdd(&d_cursor[dst], 1);
    d_packed[pos] = src | (rel << 20);
    d_ee[pos]     = make_float4(ev[0], ev[1], ev[2], ev[3]);
}

// ---------------- gather: 2 warps/dst feature-split, depth-4 unrolled ----------------
__global__ void __launch_bounds__(256) k_gather(const float* __restrict__ h,
                                                const float* __restrict__ r,
                                                const float* __restrict__ w,
                                                float* __restrict__ out, int N) {
    int gw   = (blockIdx.x * blockDim.x + threadIdx.x) >> 5;
    int lane = threadIdx.x & 31;
    int n    = gw >> 1;
    int half = gw & 1;                 // feature half: 0 -> [0,64), 1 -> [64,128)
    if (n >= N) return;
    int f0 = half * 64 + lane * 2;

    if (half == 0 && lane == 0) d_deg[n] = 0;  // reset for next replay

    // cumulative diag products, 2 features per lane, all 4 heads
    float2 w0 = *(const float2*)(w + 0 * F + f0);
    float2 w1 = *(const float2*)(w + 1 * F + f0);
    float2 w2 = *(const float2*)(w + 2 * F + f0);
    float W[4][2];
    W[0][0] = 1.f;            W[0][1] = 1.f;
    W[1][0] = w0.x;           W[1][1] = w0.y;
    W[2][0] = W[1][0] * w1.x; W[2][1] = W[1][1] * w1.y;
    W[3][0] = W[2][0] * w2.x; W[3][1] = W[2][1] * w2.y;

    ull aH[4] = {0ull, 0ull, 0ull, 0ull};
    ull aR[4] = {0ull, 0ull, 0ull, 0ull};
    float rs[4] = {0.f, 0.f, 0.f, 0.f};

    int kb = d_off[n], ke = d_off[n + 1];
    int k = kb;

    // depth-4: 4 meta loads -> 8 gather loads -> FMAs. Two waits per 4 edges.
    for (; k + 3 < ke; k += 4) {
        int    p0 = d_packed[k];
        int    p1 = d_packed[k + 1];
        int    p2 = d_packed[k + 2];
        int    p3 = d_packed[k + 3];
        float4 e0 = d_ee[k];
        float4 e1 = d_ee[k + 1];
        float4 e2 = d_ee[k + 2];
        float4 e3 = d_ee[k + 3];
        ull h0 = *(const ull*)(h + (size_t)(p0 & 0xFFFFF) * F + f0);
        ull r0 = *(const ull*)(r + (size_t)(p0 >> 20) * F + f0);
        ull h1 = *(const ull*)(h + (size_t)(p1 & 0xFFFFF) * F + f0);
        ull r1 = *(const ull*)(r + (size_t)(p1 >> 20) * F + f0);
        ull h2 = *(const ull*)(h + (size_t)(p2 & 0xFFFFF) * F + f0);
        ull r2 = *(const ull*)(r + (size_t)(p2 >> 20) * F + f0);
        ull h3 = *(const ull*)(h + (size_t)(p3 & 0xFFFFF) * F + f0);
        ull r3 = *(const ull*)(r + (size_t)(p3 >> 20) * F + f0);
        float ev0[4] = {e0.x, e0.y, e0.z, e0.w};
        float ev1[4] = {e1.x, e1.y, e1.z, e1.w};
        float ev2[4] = {e2.x, e2.y, e2.z, e2.w};
        float ev3[4] = {e3.x, e3.y, e3.z, e3.w};
#pragma unroll
        for (int i = 0; i < 4; i++) {
            ull eb0 = pk2(ev0[i], ev0[i]);
            ull eb1 = pk2(ev1[i], ev1[i]);
            ull eb2 = pk2(ev2[i], ev2[i]);
            ull eb3 = pk2(ev3[i], ev3[i]);
            aH[i] = f2fma(h0, eb0, aH[i]);
            aR[i] = f2fma(r0, eb0, aR[i]);
            aH[i] = f2fma(h1, eb1, aH[i]);
            aR[i] = f2fma(r1, eb1, aR[i]);
            aH[i] = f2fma(h2, eb2, aH[i]);
            aR[i] = f2fma(r2, eb2, aR[i]);
            aH[i] = f2fma(h3, eb3, aH[i]);
            aR[i] = f2fma(r3, eb3, aR[i]);
            rs[i] += (ev0[i] + ev1[i]) + (ev2[i] + ev3[i]);
        }
    }
    // remainder (<= 3 edges)
    for (; k < ke; k++) {
        int    p0 = d_packed[k];
        float4 e0 = d_ee[k];
        ull h0 = *(const ull*)(h + (size_t)(p0 & 0xFFFFF) * F + f0);
        ull r0 = *(const ull*)(r + (size_t)(p0 >> 20) * F + f0);
        float ev0[4] = {e0.x, e0.y, e0.z, e0.w};
#pragma unroll
        for (int i = 0; i < 4; i++) {
            ull eb = pk2(ev0[i], ev0[i]);
            aH[i] = f2fma(h0, eb, aH[i]);
            aR[i] = f2fma(r0, eb, aR[i]);
            rs[i] += ev0[i];
        }
    }

#pragma unroll
    for (int i = 0; i < 4; i++) {
        float inv = 1.f / rs[i];  // every node has >=1 in-edge by construction
        float a0, a1, b0, b1;
        upk2(a0, a1, aH[i]);
        upk2(b0, b1, aR[i]);
        float2 o = make_float2((W[i][0] * a0 - b0) * inv,
                               (W[i][1] * a1 - b1) * inv);
        *(float2*)(out + ((size_t)i * N + n) * F + f0) = o;
    }
}

extern "C" void kernel_launch(void* const* d_in, const int* in_sizes, int n_in,
                              void* d_out, int out_size) {
    const float* h      = (const float*)d_in[0];
    const float* inputr = (const float*)d_in[1];
    const float* w      = (const float*)d_in[2];
    const float* a      = (const float*)d_in[3];
    const int*   A      = (const int*)d_in[4];
    int N = in_sizes[0] / F;
    int R = in_sizes[1] / F;
    int E = in_sizes[4] / 3;
    float* out = (float*)d_out;

    int TB = (R + 3) / 4;            // t blocks (4 warps each)
    int SB = (N + 3) / 4;            // s blocks (4 warps each)
    int CB = (E + 127) / 128;        // count blocks
    int NB = (N + 255) / 256;        // scan blocks (<= 256)
    k_front<<<TB + SB + CB, 128>>>(h, inputr, w, a, A, N, R, E, TB, SB);
    k_scan1<<<NB, 256>>>(N);
    k_scan3<<<NB, 256>>>(N);
    k_scatter<<<(E + 255) / 256, 256>>>(A, E);
    k_gather<<<(2 * N + 7) / 8, 256>>>(h, inputr, w, out, N);
}